// round 1
// baseline (speedup 1.0000x reference)
#include <cuda_runtime.h>
#include <math.h>
#include <stdint.h>

#define NB 4
#define SEQ 128
#define DL 128
#define DM 16
#define SO 120
#define ROWS (NB*SEQ)        // 512

// ---------------- scratch (device globals; no allocations allowed) ----------
__device__ float g_Q[ROWS*DL];
__device__ float g_K[ROWS*DL];
__device__ float g_U[ROWS*256];
__device__ float g_attn[NB*SEQ*SEQ];

// ---------------- kernel A: Q, K, U = x@W1^T -------------------------------
__global__ void prep_kernel(const float* __restrict__ xl,
                            const float* __restrict__ Wq, const float* __restrict__ bq,
                            const float* __restrict__ Wk, const float* __restrict__ bk,
                            const float* __restrict__ W1)
{
    __shared__ float xs[DL];
    int row = blockIdx.x;
    int t = threadIdx.x;          // 0..255
    if (t < DL) xs[t] = xl[row*DL + t];
    __syncthreads();

    // Q (t<128) or K (t>=128)
    {
        const float* Wr = (t < DL) ? (Wq + t*DL) : (Wk + (t-DL)*DL);
        float acc = 0.f;
        #pragma unroll 8
        for (int k = 0; k < DL; k++) acc = fmaf(Wr[k], xs[k], acc);
        if (t < DL) g_Q[row*DL + t]        = acc + bq[t];
        else        g_K[row*DL + (t-DL)]   = acc + bk[t-DL];
    }
    // U row (256 outputs)
    {
        const float* Wr = W1 + t*DL;
        float acc = 0.f;
        #pragma unroll 8
        for (int k = 0; k < DL; k++) acc = fmaf(Wr[k], xs[k], acc);
        g_U[row*256 + t] = acc;   // b1 folded later on the j side
    }
}

// ---------------- kernel B: attention softmax ------------------------------
__global__ void attn_kernel()
{
    int row = blockIdx.x;          // b*128 + j
    int b = row >> 7;
    int i = threadIdx.x;           // 0..127
    __shared__ float qs[DL];
    __shared__ float red[SEQ];

    qs[i] = g_Q[row*DL + i];
    __syncthreads();

    const float* Kr = g_K + (b*SEQ + i)*DL;
    float acc = 0.f;
    #pragma unroll 8
    for (int k = 0; k < DL; k++) acc = fmaf(Kr[k], qs[k], acc);
    float logit = acc * 0.08838834764831845f;   // 1/sqrt(128)

    red[i] = logit; __syncthreads();
    for (int off = 64; off; off >>= 1) { if (i < off) red[i] = fmaxf(red[i], red[i+off]); __syncthreads(); }
    float mx = red[0]; __syncthreads();

    float e = expf(logit - mx);
    red[i] = e; __syncthreads();
    for (int off = 64; off; off >>= 1) { if (i < off) red[i] += red[i+off]; __syncthreads(); }
    float sm = red[0];

    g_attn[row*SEQ + i] = e / sm;
}

// ---------------- warp 16x16 matmul helpers (pad-17 shared buffers) --------
__device__ __forceinline__ void wmm(const float* __restrict__ A, const float* __restrict__ B,
                                    float acc[2][4], int r0, int c0)
{
    acc[0][0]=acc[0][1]=acc[0][2]=acc[0][3]=0.f;
    acc[1][0]=acc[1][1]=acc[1][2]=acc[1][3]=0.f;
    #pragma unroll
    for (int k = 0; k < 16; k++) {
        float a0 = A[r0*17 + k];
        float a1 = A[(r0+1)*17 + k];
        float b0 = B[k*17 + c0 + 0];
        float b1 = B[k*17 + c0 + 1];
        float b2 = B[k*17 + c0 + 2];
        float b3 = B[k*17 + c0 + 3];
        acc[0][0] = fmaf(a0,b0,acc[0][0]); acc[0][1] = fmaf(a0,b1,acc[0][1]);
        acc[0][2] = fmaf(a0,b2,acc[0][2]); acc[0][3] = fmaf(a0,b3,acc[0][3]);
        acc[1][0] = fmaf(a1,b0,acc[1][0]); acc[1][1] = fmaf(a1,b1,acc[1][1]);
        acc[1][2] = fmaf(a1,b2,acc[1][2]); acc[1][3] = fmaf(a1,b3,acc[1][3]);
    }
}

__device__ __forceinline__ void wstore(float* __restrict__ C, const float acc[2][4], int r0, int c0)
{
    #pragma unroll
    for (int ii = 0; ii < 2; ii++)
        #pragma unroll
        for (int jj = 0; jj < 4; jj++)
            C[(r0+ii)*17 + c0 + jj] = acc[ii][jj];
}

// ---------------- kernel C: pairwise MLP + expm + aggregate ----------------
// One block per (b, j). 512 threads = 16 warps. Chunks of 32 i-values.
// smem layout (floats):
//   Ujb[256] | b2s[120] | attn_r[128] | xm[2048] | settled[16]
//   H[32*256] | W2s[120*65] | lie[32*120] | mm[16 warps * 4 bufs * 272]
//   tri_r[120], tri_c[120] ints at the end
#define SM_UJB   0
#define SM_B2    (SM_UJB + 256)
#define SM_ATT   (SM_B2 + 120)
#define SM_XM    (SM_ATT + 128)
#define SM_SET   (SM_XM + 2048)
#define SM_H     (SM_SET + 16)
#define SM_W2    (SM_H + 32*256)
#define SM_LIE   (SM_W2 + 120*65)
#define SM_MM    (SM_LIE + 32*120)
#define SM_FLOATS (SM_MM + 16*4*272)
#define SM_BYTES  (SM_FLOATS*4 + 240*4)

__global__ void __launch_bounds__(512, 1)
main_kernel(const float* __restrict__ xm_g,
            const float* __restrict__ W2, const float* __restrict__ b1,
            const float* __restrict__ b2, const float* __restrict__ Wo,
            const float* __restrict__ bo,
            float* __restrict__ out, float* __restrict__ Tout)
{
    extern __shared__ float sm[];
    float* Ujb    = sm + SM_UJB;
    float* b2s    = sm + SM_B2;
    float* attn_r = sm + SM_ATT;
    float* xm     = sm + SM_XM;
    float* setl   = sm + SM_SET;
    float* H      = sm + SM_H;
    float* W2s    = sm + SM_W2;
    float* lie    = sm + SM_LIE;
    float* mmb    = sm + SM_MM;
    int*   tri_r  = (int*)(sm + SM_FLOATS);
    int*   tri_c  = tri_r + 120;

    int row  = blockIdx.x;              // b*128 + j
    int b    = row >> 7;
    int t    = threadIdx.x;
    int lane = t & 31;
    int w    = t >> 5;                  // warp 0..15

    if (t < 256) Ujb[t] = g_U[row*256 + t] + b1[t];
    if (t < 120) b2s[t] = b2[t];
    if (t < 128) attn_r[t] = g_attn[row*SEQ + t];
    if (t < 16)  setl[t] = 0.f;
    for (int idx = t; idx < SEQ*DM; idx += 512) xm[idx] = xm_g[b*SEQ*DM + idx];
    if (t < 120) {
        int l = t, r = 0, base = 0;
        while (l >= base + (15 - r)) { base += 15 - r; r++; }
        tri_r[t] = r; tri_c[t] = r + 1 + (l - base);
    }
    __syncthreads();

    float* Abuf  = mmb + w*(4*272);
    float* A2buf = Abuf + 272;
    float* A3buf = Abuf + 544;
    float* Tbuf  = Abuf + 816;

    const float c3=1.f/6.f, c4=1.f/24.f, c5=1.f/120.f;
    const float c6=1.f/720.f, c7=1.f/5040.f, c8=1.f/40320.f, c9=1.f/362880.f;

    int r0m = (lane >> 2) * 2;          // matmul row tile
    int c0m = (lane & 3)  * 4;          // matmul col tile

    for (int ch = 0; ch < 4; ch++) {
        int i0 = ch * 32;
        __syncthreads();                // previous chunk fully consumed

        // ---- H[ii][col] = tanh(Ujb[col] - U[b,i0+ii][col]) ----
        {
            int col  = t & 255;
            int half = t >> 8;
            for (int ii = half*16; ii < half*16 + 16; ii++) {
                int gi = i0 + ii;
                float u = g_U[(b*SEQ + gi)*256 + col];
                H[ii*256 + col] = tanhf(Ujb[col] - u);
            }
        }

        // ---- lie[32][120] = H @ W2^T + b2  (k tiled through shared) ----
        float acc[2][4];
        acc[0][0]=acc[0][1]=acc[0][2]=acc[0][3]=0.f;
        acc[1][0]=acc[1][1]=acc[1][2]=acc[1][3]=0.f;
        int rA = 2*w, rB = 2*w + 1;
        for (int kt = 0; kt < 256; kt += 64) {
            __syncthreads();
            for (int idx = t; idx < 120*64; idx += 512) {
                int c = idx >> 6, kk = idx & 63;
                W2s[c*65 + kk] = W2[c*256 + kt + kk];
            }
            __syncthreads();
            #pragma unroll 4
            for (int kk = 0; kk < 64; kk++) {
                float h0 = H[rA*256 + kt + kk];
                float h1 = H[rB*256 + kt + kk];
                #pragma unroll
                for (int m = 0; m < 4; m++) {
                    int c = lane + 32*m;
                    if (c < 120) {
                        float wv = W2s[c*65 + kk];
                        acc[0][m] = fmaf(h0, wv, acc[0][m]);
                        acc[1][m] = fmaf(h1, wv, acc[1][m]);
                    }
                }
            }
        }
        #pragma unroll
        for (int m = 0; m < 4; m++) {
            int c = lane + 32*m;
            if (c < 120) {
                lie[rA*120 + c] = acc[0][m] + b2s[c];
                lie[rB*120 + c] = acc[1][m] + b2s[c];
            }
        }
        __syncwarp();   // lie rows are private to this warp

        // ---- expm for this warp's two matrices ----
        for (int rr = 0; rr < 2; rr++) {
            int mi = 2*w + rr;
            int gi = i0 + mi;
            const float* lrow = lie + mi*120;

            for (int q = lane; q < 272; q += 32) Abuf[q] = 0.f;
            __syncwarp();
            #pragma unroll
            for (int m = 0; m < 4; m++) {
                int l = lane + 32*m;
                if (l < 120) {
                    float v = lrow[l];
                    int rI = tri_r[l], cI = tri_c[l];
                    Abuf[rI*17 + cI] =  v;
                    Abuf[cI*17 + rI] = -v;
                }
            }
            __syncwarp();

            // inf-norm -> scaling exponent
            int myr = lane & 15;
            float rs = 0.f;
            #pragma unroll
            for (int c = 0; c < 16; c++) rs += fabsf(Abuf[myr*17 + c]);
            #pragma unroll
            for (int off = 8; off; off >>= 1) rs = fmaxf(rs, __shfl_xor_sync(0xffffffffu, rs, off));
            int sct = 0;
            if (rs > 1.f) { sct = (int)ceilf(log2f(rs)); if (sct > 12) sct = 12; }
            float scale = ldexpf(1.f, -sct);
            for (int q = lane; q < 256; q += 32) {
                int rI = q >> 4, cI = q & 15;
                Abuf[rI*17 + cI] *= scale;
            }
            __syncwarp();

            float reg[2][4];
            // A2 = A*A
            wmm(Abuf, Abuf, reg, r0m, c0m); __syncwarp();
            wstore(A2buf, reg, r0m, c0m);   __syncwarp();
            // A3 = A2*A
            wmm(A2buf, Abuf, reg, r0m, c0m); __syncwarp();
            wstore(A3buf, reg, r0m, c0m);    __syncwarp();
            // Tbuf = B2 = c6 I + c7 A + c8 A2 + c9 A3
            for (int q = lane; q < 256; q += 32) {
                int rI = q >> 4, cI = q & 15;
                float v = fmaf(c7, Abuf[rI*17+cI],
                          fmaf(c8, A2buf[rI*17+cI], c9 * A3buf[rI*17+cI]));
                if (rI == cI) v += c6;
                Tbuf[rI*17 + cI] = v;
            }
            __syncwarp();
            // reg = A3 * B2 ; += B1 ; -> Tbuf
            wmm(A3buf, Tbuf, reg, r0m, c0m); __syncwarp();
            #pragma unroll
            for (int ii = 0; ii < 2; ii++)
                #pragma unroll
                for (int jj = 0; jj < 4; jj++) {
                    int rI = r0m + ii, cI = c0m + jj;
                    reg[ii][jj] += fmaf(c4, Abuf[rI*17+cI], c5 * A2buf[rI*17+cI]);
                    if (rI == cI) reg[ii][jj] += c3;
                }
            wstore(Tbuf, reg, r0m, c0m); __syncwarp();
            // reg = A3 * (B1 + A3*B2) + B0
            wmm(A3buf, Tbuf, reg, r0m, c0m);
            #pragma unroll
            for (int ii = 0; ii < 2; ii++)
                #pragma unroll
                for (int jj = 0; jj < 4; jj++) {
                    int rI = r0m + ii, cI = c0m + jj;
                    reg[ii][jj] += fmaf(0.5f, A2buf[rI*17+cI], Abuf[rI*17+cI]);
                    if (rI == cI) reg[ii][jj] += 1.f;
                }
            // squarings
            if (sct > 0) {
                __syncwarp();
                wstore(Tbuf, reg, r0m, c0m); __syncwarp();
                for (int q = 0; q < sct; q++) {
                    wmm(Tbuf, Tbuf, reg, r0m, c0m);
                    if (q < sct - 1) {
                        __syncwarp();
                        wstore(Tbuf, reg, r0m, c0m);
                        __syncwarp();
                    }
                }
            }

            // write T_all
            float* dst = Tout + ((size_t)row*SEQ + gi)*256;
            *(float4*)(dst + (r0m  )*16 + c0m) = make_float4(reg[0][0],reg[0][1],reg[0][2],reg[0][3]);
            *(float4*)(dst + (r0m+1)*16 + c0m) = make_float4(reg[1][0],reg[1][1],reg[1][2],reg[1][3]);

            // transported & settled
            const float* xv = xm + gi*DM;
            float p0 = reg[0][0]*xv[c0m] + reg[0][1]*xv[c0m+1] + reg[0][2]*xv[c0m+2] + reg[0][3]*xv[c0m+3];
            float p1 = reg[1][0]*xv[c0m] + reg[1][1]*xv[c0m+1] + reg[1][2]*xv[c0m+2] + reg[1][3]*xv[c0m+3];
            p0 += __shfl_xor_sync(0xffffffffu, p0, 1);
            p0 += __shfl_xor_sync(0xffffffffu, p0, 2);
            p1 += __shfl_xor_sync(0xffffffffu, p1, 1);
            p1 += __shfl_xor_sync(0xffffffffu, p1, 2);
            if ((lane & 3) == 0) {
                float wgt = attn_r[gi];
                atomicAdd(&setl[r0m    ], wgt * p0);
                atomicAdd(&setl[r0m + 1], wgt * p1);
            }
            __syncwarp();
        }
    }

    __syncthreads();
    if (t < DM) {
        float acc = bo[t];
        #pragma unroll
        for (int e = 0; e < DM; e++) acc = fmaf(Wo[t*DM + e], setl[e], acc);
        out[row*DM + t] = acc;
    }
}

// ---------------- launch ----------------------------------------------------
extern "C" void kernel_launch(void* const* d_in, const int* in_sizes, int n_in,
                              void* d_out, int out_size)
{
    const float* xl  = (const float*)d_in[0];
    const float* xmm = (const float*)d_in[1];
    const float* Wq  = (const float*)d_in[2];
    const float* bq  = (const float*)d_in[3];
    const float* Wk  = (const float*)d_in[4];
    const float* bk  = (const float*)d_in[5];
    const float* W1  = (const float*)d_in[6];
    const float* b1  = (const float*)d_in[7];
    const float* W2  = (const float*)d_in[8];
    const float* b2  = (const float*)d_in[9];
    const float* Wo  = (const float*)d_in[10];
    const float* bo  = (const float*)d_in[11];

    float* out  = (float*)d_out;
    float* Tout = out + NB*SEQ*DM;      // T_all follows out

    static bool attr_set = false;
    if (!attr_set) {
        cudaFuncSetAttribute(main_kernel, cudaFuncAttributeMaxDynamicSharedMemorySize, SM_BYTES);
        attr_set = true;
    }

    prep_kernel<<<ROWS, 256>>>(xl, Wq, bq, Wk, bk, W1);
    attn_kernel<<<ROWS, 128>>>();
    main_kernel<<<ROWS, 512, SM_BYTES>>>(xmm, W2, b1, b2, Wo, bo, out, Tout);
}

// round 2
// speedup vs baseline: 1.3565x; 1.3565x over previous
#include <cuda_runtime.h>
#include <math.h>
#include <stdint.h>

#define NB 4
#define SEQ 128
#define DL 128
#define DM 16
#define SO 120
#define ROWS (NB*SEQ)        // 512

// ---------------- scratch (device globals; no allocations allowed) ----------
__device__ float g_Q[ROWS*DL];
__device__ float g_K[ROWS*DL];
__device__ float g_U[ROWS*256];
__device__ float g_attn[NB*SEQ*SEQ];

__device__ __forceinline__ float ftanh(float x) {
    float y;
    asm("tanh.approx.f32 %0, %1;" : "=f"(y) : "f"(x));
    return y;
}

// ---------------- kernel A: tiled GEMM  C[512 x 512] = X @ [Wq;Wk;W1]^T ----
// grid (8 row-tiles, 8 col-tiles), 256 threads, 64x64 tile, k tiled by 64.
__global__ void __launch_bounds__(256)
prep_kernel(const float* __restrict__ xl,
            const float* __restrict__ Wq, const float* __restrict__ bq,
            const float* __restrict__ Wk, const float* __restrict__ bk,
            const float* __restrict__ W1)
{
    __shared__ float Xs[64*64];    // [row][k]   stride 64
    __shared__ float Wt[64*68];    // [k][col]   stride 68 (float4-aligned)

    int bx = blockIdx.x;           // row tile
    int by = blockIdx.y;           // col tile
    int t  = threadIdx.x;
    int tx = t & 15, ty = t >> 4;

    const float* src;
    if      (by < 2) src = Wq + (by    )*64*DL;
    else if (by < 4) src = Wk + (by - 2)*64*DL;
    else             src = W1 + (by - 4)*64*DL;

    float acc[4][4];
    #pragma unroll
    for (int i = 0; i < 4; i++)
        #pragma unroll
        for (int j = 0; j < 4; j++) acc[i][j] = 0.f;

    for (int k0 = 0; k0 < DL; k0 += 64) {
        __syncthreads();
        #pragma unroll
        for (int s = 0; s < 16; s++) {
            int idx = t + 256*s;           // 4096 elems
            int r = idx >> 6, k = idx & 63;
            Xs[r*64 + k] = xl[(bx*64 + r)*DL + k0 + k];
            Wt[k*68 + r] = src[r*DL + k0 + k];
        }
        __syncthreads();

        #pragma unroll 8
        for (int k = 0; k < 64; k++) {
            float4 bv = *(const float4*)&Wt[k*68 + tx*4];
            #pragma unroll
            for (int i = 0; i < 4; i++) {
                float a = Xs[(ty*4 + i)*64 + k];
                acc[i][0] = fmaf(a, bv.x, acc[i][0]);
                acc[i][1] = fmaf(a, bv.y, acc[i][1]);
                acc[i][2] = fmaf(a, bv.z, acc[i][2]);
                acc[i][3] = fmaf(a, bv.w, acc[i][3]);
            }
        }
    }

    // store with bias
    #pragma unroll
    for (int i = 0; i < 4; i++) {
        int rowg = bx*64 + ty*4 + i;
        int c0   = tx*4;
        if (by < 2) {
            int col = by*64 + c0;
            float4 v = make_float4(acc[i][0]+bq[col], acc[i][1]+bq[col+1],
                                   acc[i][2]+bq[col+2], acc[i][3]+bq[col+3]);
            *(float4*)&g_Q[rowg*DL + col] = v;
        } else if (by < 4) {
            int col = (by-2)*64 + c0;
            float4 v = make_float4(acc[i][0]+bk[col], acc[i][1]+bk[col+1],
                                   acc[i][2]+bk[col+2], acc[i][3]+bk[col+3]);
            *(float4*)&g_K[rowg*DL + col] = v;
        } else {
            int col = (by-4)*64 + c0;   // b1 folded in later on the j side
            *(float4*)&g_U[rowg*256 + col] =
                make_float4(acc[i][0], acc[i][1], acc[i][2], acc[i][3]);
        }
    }
}

// ---------------- kernel B: attention softmax ------------------------------
// grid 16: block = (b, 32-row j tile). 256 threads.
#define AT_QS 0                  // 32*128
#define AT_KT (AT_QS + 32*128)   // [k][i] 128*132
#define AT_S  (AT_KT + 128*132)  // 32*132
#define AT_FLOATS (AT_S + 32*132)
#define AT_BYTES  (AT_FLOATS*4)

__global__ void __launch_bounds__(256)
attn_kernel()
{
    extern __shared__ float sm[];
    float* Qs = sm + AT_QS;
    float* Kt = sm + AT_KT;
    float* S  = sm + AT_S;

    int b  = blockIdx.x >> 2;
    int jt = (blockIdx.x & 3) * 32;
    int t  = threadIdx.x;
    int tx = t & 15, ty = t >> 4;

    for (int idx = t; idx < 32*128; idx += 256) {
        int j = idx >> 7, k = idx & 127;
        Qs[j*128 + k] = g_Q[(b*SEQ + jt + j)*DL + k];
    }
    for (int idx = t; idx < 128*128; idx += 256) {
        int i = idx >> 7, k = idx & 127;
        Kt[k*132 + i] = g_K[(b*SEQ + i)*DL + k];
    }
    __syncthreads();

    // 2j x 8i register tile per thread
    float acc[2][8];
    #pragma unroll
    for (int i = 0; i < 2; i++)
        #pragma unroll
        for (int j = 0; j < 8; j++) acc[i][j] = 0.f;

    int j0 = ty*2, i0 = tx*8;
    #pragma unroll 4
    for (int k = 0; k < 128; k++) {
        float q0 = Qs[(j0  )*128 + k];
        float q1 = Qs[(j0+1)*128 + k];
        float4 k0v = *(const float4*)&Kt[k*132 + i0];
        float4 k1v = *(const float4*)&Kt[k*132 + i0 + 4];
        acc[0][0]=fmaf(q0,k0v.x,acc[0][0]); acc[0][1]=fmaf(q0,k0v.y,acc[0][1]);
        acc[0][2]=fmaf(q0,k0v.z,acc[0][2]); acc[0][3]=fmaf(q0,k0v.w,acc[0][3]);
        acc[0][4]=fmaf(q0,k1v.x,acc[0][4]); acc[0][5]=fmaf(q0,k1v.y,acc[0][5]);
        acc[0][6]=fmaf(q0,k1v.z,acc[0][6]); acc[0][7]=fmaf(q0,k1v.w,acc[0][7]);
        acc[1][0]=fmaf(q1,k0v.x,acc[1][0]); acc[1][1]=fmaf(q1,k0v.y,acc[1][1]);
        acc[1][2]=fmaf(q1,k0v.z,acc[1][2]); acc[1][3]=fmaf(q1,k0v.w,acc[1][3]);
        acc[1][4]=fmaf(q1,k1v.x,acc[1][4]); acc[1][5]=fmaf(q1,k1v.y,acc[1][5]);
        acc[1][6]=fmaf(q1,k1v.z,acc[1][6]); acc[1][7]=fmaf(q1,k1v.w,acc[1][7]);
    }
    const float sc = 0.08838834764831845f;  // 1/sqrt(128)
    #pragma unroll
    for (int i = 0; i < 2; i++) {
        *(float4*)&S[(j0+i)*132 + i0] =
            make_float4(acc[i][0]*sc, acc[i][1]*sc, acc[i][2]*sc, acc[i][3]*sc);
        *(float4*)&S[(j0+i)*132 + i0 + 4] =
            make_float4(acc[i][4]*sc, acc[i][5]*sc, acc[i][6]*sc, acc[i][7]*sc);
    }
    __syncthreads();

    // softmax: 8 warps x 4 rows
    int w = t >> 5, lane = t & 31;
    for (int q = 0; q < 4; q++) {
        int r = w*4 + q;
        float v0 = S[r*132 + lane      ];
        float v1 = S[r*132 + lane + 32 ];
        float v2 = S[r*132 + lane + 64 ];
        float v3 = S[r*132 + lane + 96 ];
        float mx = fmaxf(fmaxf(v0,v1), fmaxf(v2,v3));
        #pragma unroll
        for (int off = 16; off; off >>= 1)
            mx = fmaxf(mx, __shfl_xor_sync(0xffffffffu, mx, off));
        float e0 = expf(v0-mx), e1 = expf(v1-mx), e2 = expf(v2-mx), e3 = expf(v3-mx);
        float sum = e0+e1+e2+e3;
        #pragma unroll
        for (int off = 16; off; off >>= 1)
            sum += __shfl_xor_sync(0xffffffffu, sum, off);
        float inv = 1.f/sum;
        float* dst = g_attn + (b*SEQ + jt + r)*SEQ;
        dst[lane     ] = e0*inv;
        dst[lane + 32] = e1*inv;
        dst[lane + 64] = e2*inv;
        dst[lane + 96] = e3*inv;
    }
}

// ---------------- warp 16x16 matmul helpers (pad-20 shared buffers) --------
__device__ __forceinline__ void wmm(const float* __restrict__ A, const float* __restrict__ B,
                                    float acc[2][4], int r0, int c0)
{
    acc[0][0]=acc[0][1]=acc[0][2]=acc[0][3]=0.f;
    acc[1][0]=acc[1][1]=acc[1][2]=acc[1][3]=0.f;
    #pragma unroll
    for (int k = 0; k < 16; k++) {
        float a0 = A[r0*20 + k];
        float a1 = A[(r0+1)*20 + k];
        float4 bv = *(const float4*)&B[k*20 + c0];
        acc[0][0] = fmaf(a0,bv.x,acc[0][0]); acc[0][1] = fmaf(a0,bv.y,acc[0][1]);
        acc[0][2] = fmaf(a0,bv.z,acc[0][2]); acc[0][3] = fmaf(a0,bv.w,acc[0][3]);
        acc[1][0] = fmaf(a1,bv.x,acc[1][0]); acc[1][1] = fmaf(a1,bv.y,acc[1][1]);
        acc[1][2] = fmaf(a1,bv.z,acc[1][2]); acc[1][3] = fmaf(a1,bv.w,acc[1][3]);
    }
}

__device__ __forceinline__ void wstore(float* __restrict__ C, const float acc[2][4], int r0, int c0)
{
    *(float4*)&C[(r0  )*20 + c0] = make_float4(acc[0][0],acc[0][1],acc[0][2],acc[0][3]);
    *(float4*)&C[(r0+1)*20 + c0] = make_float4(acc[1][0],acc[1][1],acc[1][2],acc[1][3]);
}

// ---------------- kernel C: pairwise MLP + expm + aggregate ----------------
#define SM_UJB   0
#define SM_B2    (SM_UJB + 256)
#define SM_ATT   (SM_B2 + 120)
#define SM_XM    (SM_ATT + 128)
#define SM_SET   (SM_XM + 2048)
#define SM_H     (SM_SET + 16)
#define SM_W2    (SM_H + 32*256)
#define SM_LIE   (SM_W2 + 64*132)
#define SM_MM    (SM_LIE + 32*120)
#define SM_FLOATS (SM_MM + 16*4*320)
#define SM_BYTES  (SM_FLOATS*4 + 240*4)

__global__ void __launch_bounds__(512, 1)
main_kernel(const float* __restrict__ xm_g,
            const float* __restrict__ W2, const float* __restrict__ b1,
            const float* __restrict__ b2, const float* __restrict__ Wo,
            const float* __restrict__ bo,
            float* __restrict__ out, float* __restrict__ Tout)
{
    extern __shared__ float sm[];
    float* Ujb    = sm + SM_UJB;
    float* b2s    = sm + SM_B2;
    float* attn_r = sm + SM_ATT;
    float* xm     = sm + SM_XM;
    float* setl   = sm + SM_SET;
    float* H      = sm + SM_H;
    float* W2s    = sm + SM_W2;      // [kk][c] stride 132, cols 120..127 zeroed
    float* lie    = sm + SM_LIE;
    float* mmb    = sm + SM_MM;
    int*   tri_r  = (int*)(sm + SM_FLOATS);
    int*   tri_c  = tri_r + 120;

    int row  = blockIdx.x;              // b*128 + j
    int b    = row >> 7;
    int t    = threadIdx.x;
    int lane = t & 31;
    int w    = t >> 5;                  // warp 0..15

    if (t < 256) Ujb[t] = g_U[row*256 + t] + b1[t];
    if (t < 120) b2s[t] = b2[t];
    if (t < 128) attn_r[t] = g_attn[row*SEQ + t];
    if (t < 16)  setl[t] = 0.f;
    for (int idx = t; idx < SEQ*DM; idx += 512) xm[idx] = xm_g[b*SEQ*DM + idx];
    if (t < 120) {
        int l = t, r = 0, base = 0;
        while (l >= base + (15 - r)) { base += 15 - r; r++; }
        tri_r[t] = r; tri_c[t] = r + 1 + (l - base);
    }
    __syncthreads();

    float* Abuf  = mmb + w*(4*320);
    float* A2buf = Abuf + 320;
    float* A3buf = Abuf + 640;
    float* Tbuf  = Abuf + 960;

    const float c3=1.f/6.f, c4=1.f/24.f, c5=1.f/120.f;
    const float c6=1.f/720.f, c7=1.f/5040.f, c8=1.f/40320.f, c9=1.f/362880.f;

    int r0m = (lane >> 2) * 2;          // matmul row tile
    int c0m = (lane & 3)  * 4;          // matmul col tile

    for (int ch = 0; ch < 4; ch++) {
        int i0 = ch * 32;
        __syncthreads();                // previous chunk fully consumed

        // ---- H[ii][col] = tanh(Ujb[col] - U[b,i0+ii][col]) ----
        {
            int col  = t & 255;
            int half = t >> 8;
            for (int ii = half*16; ii < half*16 + 16; ii++) {
                int gi = i0 + ii;
                float u = g_U[(b*SEQ + gi)*256 + col];
                H[ii*256 + col] = ftanh(Ujb[col] - u);
            }
        }

        // ---- lie[32][120] = H @ W2^T + b2  (k tiled through shared) ----
        float acc[2][4];
        acc[0][0]=acc[0][1]=acc[0][2]=acc[0][3]=0.f;
        acc[1][0]=acc[1][1]=acc[1][2]=acc[1][3]=0.f;
        int rA = 2*w, rB = 2*w + 1;
        int cbase = lane*4;
        for (int kt = 0; kt < 256; kt += 64) {
            __syncthreads();
            for (int idx = t; idx < 120*64; idx += 512) {
                int c = idx >> 6, kk = idx & 63;
                W2s[kk*132 + c] = W2[c*256 + kt + kk];   // transposed stage
            }
            if (t < 512) {               // zero pad cols 120..127
                int kk = t >> 3, c = 120 + (t & 7);
                W2s[kk*132 + c] = 0.f;
            }
            __syncthreads();
            #pragma unroll 4
            for (int kk = 0; kk < 64; kk++) {
                float h0 = H[rA*256 + kt + kk];
                float h1 = H[rB*256 + kt + kk];
                float4 wv = *(const float4*)&W2s[kk*132 + cbase];
                acc[0][0]=fmaf(h0,wv.x,acc[0][0]); acc[0][1]=fmaf(h0,wv.y,acc[0][1]);
                acc[0][2]=fmaf(h0,wv.z,acc[0][2]); acc[0][3]=fmaf(h0,wv.w,acc[0][3]);
                acc[1][0]=fmaf(h1,wv.x,acc[1][0]); acc[1][1]=fmaf(h1,wv.y,acc[1][1]);
                acc[1][2]=fmaf(h1,wv.z,acc[1][2]); acc[1][3]=fmaf(h1,wv.w,acc[1][3]);
            }
        }
        #pragma unroll
        for (int m = 0; m < 4; m++) {
            int c = cbase + m;
            if (c < 120) {
                lie[rA*120 + c] = acc[0][m] + b2s[c];
                lie[rB*120 + c] = acc[1][m] + b2s[c];
            }
        }
        __syncwarp();   // lie rows are private to this warp

        // ---- expm for this warp's two matrices ----
        for (int rr = 0; rr < 2; rr++) {
            int mi = 2*w + rr;
            int gi = i0 + mi;
            const float* lrow = lie + mi*120;

            for (int q = lane; q < 320; q += 32) Abuf[q] = 0.f;
            __syncwarp();
            #pragma unroll
            for (int m = 0; m < 4; m++) {
                int l = lane + 32*m;
                if (l < 120) {
                    float v = lrow[l];
                    int rI = tri_r[l], cI = tri_c[l];
                    Abuf[rI*20 + cI] =  v;
                    Abuf[cI*20 + rI] = -v;
                }
            }
            __syncwarp();

            // inf-norm -> scaling exponent
            int myr = lane & 15;
            float rs = 0.f;
            #pragma unroll
            for (int c = 0; c < 16; c++) rs += fabsf(Abuf[myr*20 + c]);
            #pragma unroll
            for (int off = 8; off; off >>= 1) rs = fmaxf(rs, __shfl_xor_sync(0xffffffffu, rs, off));
            int sct = 0;
            if (rs > 1.f) { sct = (int)ceilf(log2f(rs)); if (sct > 12) sct = 12; }
            float scale = ldexpf(1.f, -sct);
            for (int q = lane; q < 256; q += 32) {
                int rI = q >> 4, cI = q & 15;
                Abuf[rI*20 + cI] *= scale;
            }
            __syncwarp();

            float reg[2][4];
            // A2 = A*A
            wmm(Abuf, Abuf, reg, r0m, c0m); __syncwarp();
            wstore(A2buf, reg, r0m, c0m);   __syncwarp();
            // A3 = A2*A
            wmm(A2buf, Abuf, reg, r0m, c0m); __syncwarp();
            wstore(A3buf, reg, r0m, c0m);    __syncwarp();
            // Tbuf = B2 = c6 I + c7 A + c8 A2 + c9 A3
            for (int q = lane; q < 256; q += 32) {
                int rI = q >> 4, cI = q & 15;
                float v = fmaf(c7, Abuf[rI*20+cI],
                          fmaf(c8, A2buf[rI*20+cI], c9 * A3buf[rI*20+cI]));
                if (rI == cI) v += c6;
                Tbuf[rI*20 + cI] = v;
            }
            __syncwarp();
            // reg = A3 * B2 ; += B1 ; -> Tbuf
            wmm(A3buf, Tbuf, reg, r0m, c0m); __syncwarp();
            #pragma unroll
            for (int ii = 0; ii < 2; ii++)
                #pragma unroll
                for (int jj = 0; jj < 4; jj++) {
                    int rI = r0m + ii, cI = c0m + jj;
                    reg[ii][jj] += fmaf(c4, Abuf[rI*20+cI], c5 * A2buf[rI*20+cI]);
                    if (rI == cI) reg[ii][jj] += c3;
                }
            wstore(Tbuf, reg, r0m, c0m); __syncwarp();
            // reg = A3 * (B1 + A3*B2) + B0
            wmm(A3buf, Tbuf, reg, r0m, c0m);
            #pragma unroll
            for (int ii = 0; ii < 2; ii++)
                #pragma unroll
                for (int jj = 0; jj < 4; jj++) {
                    int rI = r0m + ii, cI = c0m + jj;
                    reg[ii][jj] += fmaf(0.5f, A2buf[rI*20+cI], Abuf[rI*20+cI]);
                    if (rI == cI) reg[ii][jj] += 1.f;
                }
            // squarings
            if (sct > 0) {
                __syncwarp();
                wstore(Tbuf, reg, r0m, c0m); __syncwarp();
                for (int q = 0; q < sct; q++) {
                    wmm(Tbuf, Tbuf, reg, r0m, c0m);
                    if (q < sct - 1) {
                        __syncwarp();
                        wstore(Tbuf, reg, r0m, c0m);
                        __syncwarp();
                    }
                }
            }

            // write T_all
            float* dst = Tout + ((size_t)row*SEQ + gi)*256;
            *(float4*)(dst + (r0m  )*16 + c0m) = make_float4(reg[0][0],reg[0][1],reg[0][2],reg[0][3]);
            *(float4*)(dst + (r0m+1)*16 + c0m) = make_float4(reg[1][0],reg[1][1],reg[1][2],reg[1][3]);

            // transported & settled
            const float* xv = xm + gi*DM;
            float p0 = reg[0][0]*xv[c0m] + reg[0][1]*xv[c0m+1] + reg[0][2]*xv[c0m+2] + reg[0][3]*xv[c0m+3];
            float p1 = reg[1][0]*xv[c0m] + reg[1][1]*xv[c0m+1] + reg[1][2]*xv[c0m+2] + reg[1][3]*xv[c0m+3];
            p0 += __shfl_xor_sync(0xffffffffu, p0, 1);
            p0 += __shfl_xor_sync(0xffffffffu, p0, 2);
            p1 += __shfl_xor_sync(0xffffffffu, p1, 1);
            p1 += __shfl_xor_sync(0xffffffffu, p1, 2);
            if ((lane & 3) == 0) {
                float wgt = attn_r[gi];
                atomicAdd(&setl[r0m    ], wgt * p0);
                atomicAdd(&setl[r0m + 1], wgt * p1);
            }
            __syncwarp();
        }
    }

    __syncthreads();
    if (t < DM) {
        float acc = bo[t];
        #pragma unroll
        for (int e = 0; e < DM; e++) acc = fmaf(Wo[t*DM + e], setl[e], acc);
        out[row*DM + t] = acc;
    }
}

// ---------------- launch ----------------------------------------------------
extern "C" void kernel_launch(void* const* d_in, const int* in_sizes, int n_in,
                              void* d_out, int out_size)
{
    const float* xl  = (const float*)d_in[0];
    const float* xmm = (const float*)d_in[1];
    const float* Wq  = (const float*)d_in[2];
    const float* bq  = (const float*)d_in[3];
    const float* Wk  = (const float*)d_in[4];
    const float* bk  = (const float*)d_in[5];
    const float* W1  = (const float*)d_in[6];
    const float* b1  = (const float*)d_in[7];
    const float* W2  = (const float*)d_in[8];
    const float* b2  = (const float*)d_in[9];
    const float* Wo  = (const float*)d_in[10];
    const float* bo  = (const float*)d_in[11];

    float* out  = (float*)d_out;
    float* Tout = out + NB*SEQ*DM;      // T_all follows out

    static bool attr_set = false;
    if (!attr_set) {
        cudaFuncSetAttribute(main_kernel, cudaFuncAttributeMaxDynamicSharedMemorySize, SM_BYTES);
        cudaFuncSetAttribute(attn_kernel, cudaFuncAttributeMaxDynamicSharedMemorySize, AT_BYTES);
        attr_set = true;
    }

    prep_kernel<<<dim3(8,8), 256>>>(xl, Wq, bq, Wk, bk, W1);
    attn_kernel<<<16, 256, AT_BYTES>>>();
    main_kernel<<<ROWS, 512, SM_BYTES>>>(xmm, W2, b1, b2, Wo, bo, out, Tout);
}

// round 3
// speedup vs baseline: 1.9807x; 1.4602x over previous
#include <cuda_runtime.h>
#include <math.h>
#include <stdint.h>

#define NB 4
#define SEQ 128
#define DL 128
#define DM 16
#define SO 120
#define ROWS (NB*SEQ)        // 512

// ---------------- scratch (device globals; no allocations allowed) ----------
__device__ float g_Q[ROWS*DL];
__device__ float g_K[ROWS*DL];
__device__ float g_U[ROWS*256];
__device__ float g_attn[NB*SEQ*SEQ];
__device__ float g_lie[(size_t)NB*SEQ*SEQ*SO];   // 31.5 MB
__device__ float g_settled[ROWS*DM];

__constant__ int c_tri_r[120] = {
 0,0,0,0,0,0,0,0,0,0,0,0,0,0,0,
 1,1,1,1,1,1,1,1,1,1,1,1,1,1,
 2,2,2,2,2,2,2,2,2,2,2,2,2,
 3,3,3,3,3,3,3,3,3,3,3,3,
 4,4,4,4,4,4,4,4,4,4,4,
 5,5,5,5,5,5,5,5,5,5,
 6,6,6,6,6,6,6,6,6,
 7,7,7,7,7,7,7,7,
 8,8,8,8,8,8,8,
 9,9,9,9,9,9,
 10,10,10,10,10,
 11,11,11,11,
 12,12,12,
 13,13,
 14};
__constant__ int c_tri_c[120] = {
 1,2,3,4,5,6,7,8,9,10,11,12,13,14,15,
 2,3,4,5,6,7,8,9,10,11,12,13,14,15,
 3,4,5,6,7,8,9,10,11,12,13,14,15,
 4,5,6,7,8,9,10,11,12,13,14,15,
 5,6,7,8,9,10,11,12,13,14,15,
 6,7,8,9,10,11,12,13,14,15,
 7,8,9,10,11,12,13,14,15,
 8,9,10,11,12,13,14,15,
 9,10,11,12,13,14,15,
 10,11,12,13,14,15,
 11,12,13,14,15,
 12,13,14,15,
 13,14,15,
 14,15,
 15};

__device__ __forceinline__ float ftanh(float x) {
    float y;
    asm("tanh.approx.f32 %0, %1;" : "=f"(y) : "f"(x));
    return y;
}

// ---------------- kernel A: tiled GEMM  C[512 x 512] = X @ [Wq;Wk;W1]^T ----
__global__ void __launch_bounds__(256)
prep_kernel(const float* __restrict__ xl,
            const float* __restrict__ Wq, const float* __restrict__ bq,
            const float* __restrict__ Wk, const float* __restrict__ bk,
            const float* __restrict__ W1)
{
    __shared__ float Xs[64*64];
    __shared__ float Wt[64*68];

    int bx = blockIdx.x, by = blockIdx.y;
    int t  = threadIdx.x;
    int tx = t & 15, ty = t >> 4;

    const float* src;
    if      (by < 2) src = Wq + (by    )*64*DL;
    else if (by < 4) src = Wk + (by - 2)*64*DL;
    else             src = W1 + (by - 4)*64*DL;

    float acc[4][4];
    #pragma unroll
    for (int i = 0; i < 4; i++)
        #pragma unroll
        for (int j = 0; j < 4; j++) acc[i][j] = 0.f;

    for (int k0 = 0; k0 < DL; k0 += 64) {
        __syncthreads();
        #pragma unroll
        for (int s = 0; s < 16; s++) {
            int idx = t + 256*s;
            int r = idx >> 6, k = idx & 63;
            Xs[r*64 + k] = xl[(bx*64 + r)*DL + k0 + k];
            Wt[k*68 + r] = src[r*DL + k0 + k];
        }
        __syncthreads();

        #pragma unroll 8
        for (int k = 0; k < 64; k++) {
            float4 bv = *(const float4*)&Wt[k*68 + tx*4];
            #pragma unroll
            for (int i = 0; i < 4; i++) {
                float a = Xs[(ty*4 + i)*64 + k];
                acc[i][0] = fmaf(a, bv.x, acc[i][0]);
                acc[i][1] = fmaf(a, bv.y, acc[i][1]);
                acc[i][2] = fmaf(a, bv.z, acc[i][2]);
                acc[i][3] = fmaf(a, bv.w, acc[i][3]);
            }
        }
    }

    #pragma unroll
    for (int i = 0; i < 4; i++) {
        int rowg = bx*64 + ty*4 + i;
        int c0   = tx*4;
        if (by < 2) {
            int col = by*64 + c0;
            *(float4*)&g_Q[rowg*DL + col] =
                make_float4(acc[i][0]+bq[col], acc[i][1]+bq[col+1],
                            acc[i][2]+bq[col+2], acc[i][3]+bq[col+3]);
        } else if (by < 4) {
            int col = (by-2)*64 + c0;
            *(float4*)&g_K[rowg*DL + col] =
                make_float4(acc[i][0]+bk[col], acc[i][1]+bk[col+1],
                            acc[i][2]+bk[col+2], acc[i][3]+bk[col+3]);
        } else {
            int col = (by-4)*64 + c0;
            *(float4*)&g_U[rowg*256 + col] =
                make_float4(acc[i][0], acc[i][1], acc[i][2], acc[i][3]);
        }
    }
}

// ---------------- kernel B: attention softmax (+ zero g_settled) -----------
#define AT_QS 0
#define AT_KT (AT_QS + 32*128)
#define AT_S  (AT_KT + 128*132)
#define AT_FLOATS (AT_S + 32*132)
#define AT_BYTES  (AT_FLOATS*4)

__global__ void __launch_bounds__(256)
attn_kernel()
{
    extern __shared__ float sm[];
    float* Qs = sm + AT_QS;
    float* Kt = sm + AT_KT;
    float* S  = sm + AT_S;

    int b  = blockIdx.x >> 2;
    int jt = (blockIdx.x & 3) * 32;
    int t  = threadIdx.x;
    int tx = t & 15, ty = t >> 4;

    // zero g_settled slice
    for (int z = t; z < 512; z += 256) g_settled[blockIdx.x*512 + z] = 0.f;

    for (int idx = t; idx < 32*128; idx += 256) {
        int j = idx >> 7, k = idx & 127;
        Qs[j*128 + k] = g_Q[(b*SEQ + jt + j)*DL + k];
    }
    for (int idx = t; idx < 128*128; idx += 256) {
        int i = idx >> 7, k = idx & 127;
        Kt[k*132 + i] = g_K[(b*SEQ + i)*DL + k];
    }
    __syncthreads();

    float acc[2][8];
    #pragma unroll
    for (int i = 0; i < 2; i++)
        #pragma unroll
        for (int j = 0; j < 8; j++) acc[i][j] = 0.f;

    int j0 = ty*2, i0 = tx*8;
    #pragma unroll 4
    for (int k = 0; k < 128; k++) {
        float q0 = Qs[(j0  )*128 + k];
        float q1 = Qs[(j0+1)*128 + k];
        float4 k0v = *(const float4*)&Kt[k*132 + i0];
        float4 k1v = *(const float4*)&Kt[k*132 + i0 + 4];
        acc[0][0]=fmaf(q0,k0v.x,acc[0][0]); acc[0][1]=fmaf(q0,k0v.y,acc[0][1]);
        acc[0][2]=fmaf(q0,k0v.z,acc[0][2]); acc[0][3]=fmaf(q0,k0v.w,acc[0][3]);
        acc[0][4]=fmaf(q0,k1v.x,acc[0][4]); acc[0][5]=fmaf(q0,k1v.y,acc[0][5]);
        acc[0][6]=fmaf(q0,k1v.z,acc[0][6]); acc[0][7]=fmaf(q0,k1v.w,acc[0][7]);
        acc[1][0]=fmaf(q1,k0v.x,acc[1][0]); acc[1][1]=fmaf(q1,k0v.y,acc[1][1]);
        acc[1][2]=fmaf(q1,k0v.z,acc[1][2]); acc[1][3]=fmaf(q1,k0v.w,acc[1][3]);
        acc[1][4]=fmaf(q1,k1v.x,acc[1][4]); acc[1][5]=fmaf(q1,k1v.y,acc[1][5]);
        acc[1][6]=fmaf(q1,k1v.z,acc[1][6]); acc[1][7]=fmaf(q1,k1v.w,acc[1][7]);
    }
    const float sc = 0.08838834764831845f;
    #pragma unroll
    for (int i = 0; i < 2; i++) {
        *(float4*)&S[(j0+i)*132 + i0] =
            make_float4(acc[i][0]*sc, acc[i][1]*sc, acc[i][2]*sc, acc[i][3]*sc);
        *(float4*)&S[(j0+i)*132 + i0 + 4] =
            make_float4(acc[i][4]*sc, acc[i][5]*sc, acc[i][6]*sc, acc[i][7]*sc);
    }
    __syncthreads();

    int w = t >> 5, lane = t & 31;
    for (int q = 0; q < 4; q++) {
        int r = w*4 + q;
        float v0 = S[r*132 + lane      ];
        float v1 = S[r*132 + lane + 32 ];
        float v2 = S[r*132 + lane + 64 ];
        float v3 = S[r*132 + lane + 96 ];
        float mx = fmaxf(fmaxf(v0,v1), fmaxf(v2,v3));
        #pragma unroll
        for (int off = 16; off; off >>= 1)
            mx = fmaxf(mx, __shfl_xor_sync(0xffffffffu, mx, off));
        float e0 = expf(v0-mx), e1 = expf(v1-mx), e2 = expf(v2-mx), e3 = expf(v3-mx);
        float sum = e0+e1+e2+e3;
        #pragma unroll
        for (int off = 16; off; off >>= 1)
            sum += __shfl_xor_sync(0xffffffffu, sum, off);
        float inv = 1.f/sum;
        float* dst = g_attn + (b*SEQ + jt + r)*SEQ;
        dst[lane     ] = e0*inv;
        dst[lane + 32] = e1*inv;
        dst[lane + 64] = e2*inv;
        dst[lane + 96] = e3*inv;
    }
}

// ---------------- kernel C: pairwise MLP GEMM -> g_lie ---------------------
// Block = (b,j). 128 i x 128 c (c padded 120->128), 256 threads, 8x8 tiles.
__global__ void __launch_bounds__(256, 2)
pair_kernel(const float* __restrict__ b1, const float* __restrict__ W2,
            const float* __restrict__ b2)
{
    __shared__ float Ujb[256];
    __shared__ float As[32*132];   // [kk][i]
    __shared__ float Bs[32*132];   // [kk][c]

    int row = blockIdx.x;          // b*128 + j
    int b   = row >> 7;
    int t   = threadIdx.x;

    Ujb[t] = g_U[row*256 + t] + b1[t];

    int i0 = (t & 15) * 8;
    int c0 = (t >> 4) * 8;

    float acc[8][8];
    #pragma unroll
    for (int i = 0; i < 8; i++)
        #pragma unroll
        for (int j = 0; j < 8; j++) acc[i][j] = 0.f;

    for (int k0 = 0; k0 < 256; k0 += 32) {
        __syncthreads();
        // stage A: tanh(Ujb[k] - U[b,i][k]), transposed to [kk][i]
        #pragma unroll
        for (int s = 0; s < 16; s++) {
            int idx = t + 256*s;          // 4096
            int i = idx >> 5, kk = idx & 31;
            float u = g_U[(b*SEQ + i)*256 + k0 + kk];
            As[kk*132 + i] = ftanh(Ujb[k0 + kk] - u);
        }
        // stage B: W2 transposed to [kk][c]
        #pragma unroll
        for (int s = 0; s < 15; s++) {
            int idx = t + 256*s;          // 3840
            int c = idx >> 5, kk = idx & 31;
            Bs[kk*132 + c] = W2[c*256 + k0 + kk];
        }
        { int c = 120 + (t >> 5), kk = t & 31; Bs[kk*132 + c] = 0.f; }
        __syncthreads();

        #pragma unroll
        for (int kk = 0; kk < 32; kk++) {
            float4 aA = *(const float4*)&As[kk*132 + i0];
            float4 aB = *(const float4*)&As[kk*132 + i0 + 4];
            float4 bA = *(const float4*)&Bs[kk*132 + c0];
            float4 bB = *(const float4*)&Bs[kk*132 + c0 + 4];
            float av[8] = {aA.x,aA.y,aA.z,aA.w,aB.x,aB.y,aB.z,aB.w};
            float bv[8] = {bA.x,bA.y,bA.z,bA.w,bB.x,bB.y,bB.z,bB.w};
            #pragma unroll
            for (int i = 0; i < 8; i++)
                #pragma unroll
                for (int j = 0; j < 8; j++)
                    acc[i][j] = fmaf(av[i], bv[j], acc[i][j]);
        }
    }

    if (c0 < SO) {
        float4 bb0 = *(const float4*)&b2[c0];
        float4 bb1 = *(const float4*)&b2[c0 + 4];
        #pragma unroll
        for (int ii = 0; ii < 8; ii++) {
            size_t p = (size_t)row*SEQ + (i0 + ii);
            float* dst = g_lie + p*SO + c0;
            *(float4*)dst =
                make_float4(acc[ii][0]+bb0.x, acc[ii][1]+bb0.y,
                            acc[ii][2]+bb0.z, acc[ii][3]+bb0.w);
            *(float4*)(dst+4) =
                make_float4(acc[ii][4]+bb1.x, acc[ii][5]+bb1.y,
                            acc[ii][6]+bb1.z, acc[ii][7]+bb1.w);
        }
    }
}

// ---------------- warp 16x16 matmul, A preloaded to registers --------------
__device__ __forceinline__ void wmm_pre(const float* __restrict__ A,
                                        const float* __restrict__ B,
                                        float reg[2][4], int r0, int c0)
{
    float a0[16], a1[16];
    #pragma unroll
    for (int q = 0; q < 4; q++) {
        float4 v0 = *(const float4*)&A[(r0  )*20 + 4*q];
        float4 v1 = *(const float4*)&A[(r0+1)*20 + 4*q];
        a0[4*q]=v0.x; a0[4*q+1]=v0.y; a0[4*q+2]=v0.z; a0[4*q+3]=v0.w;
        a1[4*q]=v1.x; a1[4*q+1]=v1.y; a1[4*q+2]=v1.z; a1[4*q+3]=v1.w;
    }
    reg[0][0]=reg[0][1]=reg[0][2]=reg[0][3]=0.f;
    reg[1][0]=reg[1][1]=reg[1][2]=reg[1][3]=0.f;
    #pragma unroll
    for (int k = 0; k < 16; k++) {
        float4 bv = *(const float4*)&B[k*20 + c0];
        reg[0][0]=fmaf(a0[k],bv.x,reg[0][0]); reg[0][1]=fmaf(a0[k],bv.y,reg[0][1]);
        reg[0][2]=fmaf(a0[k],bv.z,reg[0][2]); reg[0][3]=fmaf(a0[k],bv.w,reg[0][3]);
        reg[1][0]=fmaf(a1[k],bv.x,reg[1][0]); reg[1][1]=fmaf(a1[k],bv.y,reg[1][1]);
        reg[1][2]=fmaf(a1[k],bv.z,reg[1][2]); reg[1][3]=fmaf(a1[k],bv.w,reg[1][3]);
    }
}

__device__ __forceinline__ void wstore20(float* __restrict__ C, const float reg[2][4],
                                         int r0, int c0)
{
    *(float4*)&C[(r0  )*20 + c0] = make_float4(reg[0][0],reg[0][1],reg[0][2],reg[0][3]);
    *(float4*)&C[(r0+1)*20 + c0] = make_float4(reg[1][0],reg[1][1],reg[1][2],reg[1][3]);
}

// ---------------- kernel D: expm + aggregate -------------------------------
// grid 1024, 128 threads = 4 warps, 16 matrices per warp, no block syncs.
__global__ void __launch_bounds__(128, 5)
expm_kernel(const float* __restrict__ xm_g, float* __restrict__ Tout)
{
    __shared__ float mm[4*4*320];
    int t = threadIdx.x, lane = t & 31, w = t >> 5;
    float* Abuf  = mm + w*1280;
    float* A2buf = Abuf + 320;
    float* A3buf = Abuf + 640;
    float* Tbuf  = Abuf + 960;

    int r0m = (lane >> 2) * 2;
    int c0m = (lane & 3)  * 4;

    const float c3=1.f/6.f, c4=1.f/24.f, c5=1.f/120.f;
    const float c6=1.f/720.f, c7=1.f/5040.f, c8=1.f/40320.f, c9=1.f/362880.f;

    int p0 = blockIdx.x*64 + w*16;

    for (int m = 0; m < 16; m++) {
        int p   = p0 + m;
        int row = p >> 7;
        int i   = p & 127;
        int b   = row >> 7;

        // scatter lie -> skew A (diag zeroed, off-diag fully covered)
        const float* lrow = g_lie + (size_t)p*SO;
        if (lane < 16) Abuf[lane*20 + lane] = 0.f;
        #pragma unroll
        for (int q = 0; q < 4; q++) {
            int l = lane + 32*q;
            if (l < SO) {
                float v = lrow[l];
                int rI = c_tri_r[l], cI = c_tri_c[l];
                Abuf[rI*20 + cI] =  v;
                Abuf[cI*20 + rI] = -v;
            }
        }
        __syncwarp();

        // inf-norm -> scaling exponent
        int myr = lane & 15;
        float4 n0 = *(const float4*)&Abuf[myr*20     ];
        float4 n1 = *(const float4*)&Abuf[myr*20 +  4];
        float4 n2 = *(const float4*)&Abuf[myr*20 +  8];
        float4 n3 = *(const float4*)&Abuf[myr*20 + 12];
        float rs = fabsf(n0.x)+fabsf(n0.y)+fabsf(n0.z)+fabsf(n0.w)
                 + fabsf(n1.x)+fabsf(n1.y)+fabsf(n1.z)+fabsf(n1.w)
                 + fabsf(n2.x)+fabsf(n2.y)+fabsf(n2.z)+fabsf(n2.w)
                 + fabsf(n3.x)+fabsf(n3.y)+fabsf(n3.z)+fabsf(n3.w);
        #pragma unroll
        for (int off = 8; off; off >>= 1)
            rs = fmaxf(rs, __shfl_xor_sync(0xffffffffu, rs, off));
        int sct = 0;
        if (rs > 1.f) { sct = (int)ceilf(log2f(rs)); if (sct > 12) sct = 12; }
        float scale = __uint_as_float((uint32_t)(127 - sct) << 23);
        #pragma unroll
        for (int q = 0; q < 8; q++) {
            int e = lane + 32*q;
            int rI = e >> 4, cI = e & 15;
            Abuf[rI*20 + cI] *= scale;
        }
        __syncwarp();

        float reg[2][4];
        // A2
        wmm_pre(Abuf, Abuf, reg, r0m, c0m);
        wstore20(A2buf, reg, r0m, c0m);  __syncwarp();
        // A3
        wmm_pre(A2buf, Abuf, reg, r0m, c0m);
        wstore20(A3buf, reg, r0m, c0m);  __syncwarp();

        // tile loads of A/A2/A3 at this lane's tile (reused below)
        float4 tA0  = *(const float4*)&Abuf [(r0m  )*20 + c0m];
        float4 tA1  = *(const float4*)&Abuf [(r0m+1)*20 + c0m];
        float4 tA20 = *(const float4*)&A2buf[(r0m  )*20 + c0m];
        float4 tA21 = *(const float4*)&A2buf[(r0m+1)*20 + c0m];
        float4 tA30 = *(const float4*)&A3buf[(r0m  )*20 + c0m];
        float4 tA31 = *(const float4*)&A3buf[(r0m+1)*20 + c0m];
        float tA [2][4] = {{tA0.x,tA0.y,tA0.z,tA0.w},{tA1.x,tA1.y,tA1.z,tA1.w}};
        float tA2[2][4] = {{tA20.x,tA20.y,tA20.z,tA20.w},{tA21.x,tA21.y,tA21.z,tA21.w}};
        float tA3[2][4] = {{tA30.x,tA30.y,tA30.z,tA30.w},{tA31.x,tA31.y,tA31.z,tA31.w}};

        // B2 = c6 I + c7 A + c8 A2 + c9 A3  -> Tbuf
        #pragma unroll
        for (int ii = 0; ii < 2; ii++)
            #pragma unroll
            for (int jj = 0; jj < 4; jj++) {
                float v = fmaf(c7, tA[ii][jj], fmaf(c8, tA2[ii][jj], c9 * tA3[ii][jj]));
                if (r0m + ii == c0m + jj) v += c6;
                reg[ii][jj] = v;
            }
        wstore20(Tbuf, reg, r0m, c0m);  __syncwarp();

        // reg = A3*B2 + B1 -> Tbuf
        wmm_pre(A3buf, Tbuf, reg, r0m, c0m);  __syncwarp();
        #pragma unroll
        for (int ii = 0; ii < 2; ii++)
            #pragma unroll
            for (int jj = 0; jj < 4; jj++) {
                reg[ii][jj] += fmaf(c4, tA[ii][jj], c5 * tA2[ii][jj]);
                if (r0m + ii == c0m + jj) reg[ii][jj] += c3;
            }
        wstore20(Tbuf, reg, r0m, c0m);  __syncwarp();

        // reg = A3*(B1 + A3*B2) + B0
        wmm_pre(A3buf, Tbuf, reg, r0m, c0m);
        #pragma unroll
        for (int ii = 0; ii < 2; ii++)
            #pragma unroll
            for (int jj = 0; jj < 4; jj++) {
                reg[ii][jj] += fmaf(0.5f, tA2[ii][jj], tA[ii][jj]);
                if (r0m + ii == c0m + jj) reg[ii][jj] += 1.f;
            }

        // squarings
        for (int q = 0; q < sct; q++) {
            __syncwarp();
            wstore20(Tbuf, reg, r0m, c0m);
            __syncwarp();
            wmm_pre(Tbuf, Tbuf, reg, r0m, c0m);
        }

        // write T_all
        float* dst = Tout + (size_t)p*256;
        *(float4*)(dst + (r0m  )*16 + c0m) = make_float4(reg[0][0],reg[0][1],reg[0][2],reg[0][3]);
        *(float4*)(dst + (r0m+1)*16 + c0m) = make_float4(reg[1][0],reg[1][1],reg[1][2],reg[1][3]);

        // transported & settled
        float4 xv = *(const float4*)&xm_g[((size_t)b*SEQ + i)*DM + c0m];
        float p0v = reg[0][0]*xv.x + reg[0][1]*xv.y + reg[0][2]*xv.z + reg[0][3]*xv.w;
        float p1v = reg[1][0]*xv.x + reg[1][1]*xv.y + reg[1][2]*xv.z + reg[1][3]*xv.w;
        p0v += __shfl_xor_sync(0xffffffffu, p0v, 1);
        p0v += __shfl_xor_sync(0xffffffffu, p0v, 2);
        p1v += __shfl_xor_sync(0xffffffffu, p1v, 1);
        p1v += __shfl_xor_sync(0xffffffffu, p1v, 2);
        if ((lane & 3) == 0) {
            float wgt = g_attn[row*SEQ + i];
            atomicAdd(&g_settled[row*DM + r0m    ], wgt * p0v);
            atomicAdd(&g_settled[row*DM + r0m + 1], wgt * p1v);
        }
        __syncwarp();
    }
}

// ---------------- kernel E: out projection ---------------------------------
__global__ void __launch_bounds__(256)
out_kernel(const float* __restrict__ Wo, const float* __restrict__ bo,
           float* __restrict__ out)
{
    int gid = blockIdx.x*256 + threadIdx.x;    // 8192
    int row = gid >> 4, d = gid & 15;
    float acc = bo[d];
    #pragma unroll
    for (int e = 0; e < DM; e++)
        acc = fmaf(Wo[d*DM + e], g_settled[row*DM + e], acc);
    out[gid] = acc;
}

// ---------------- launch ----------------------------------------------------
extern "C" void kernel_launch(void* const* d_in, const int* in_sizes, int n_in,
                              void* d_out, int out_size)
{
    const float* xl  = (const float*)d_in[0];
    const float* xmm = (const float*)d_in[1];
    const float* Wq  = (const float*)d_in[2];
    const float* bq  = (const float*)d_in[3];
    const float* Wk  = (const float*)d_in[4];
    const float* bk  = (const float*)d_in[5];
    const float* W1  = (const float*)d_in[6];
    const float* b1  = (const float*)d_in[7];
    const float* W2  = (const float*)d_in[8];
    const float* b2  = (const float*)d_in[9];
    const float* Wo  = (const float*)d_in[10];
    const float* bo  = (const float*)d_in[11];

    float* out  = (float*)d_out;
    float* Tout = out + NB*SEQ*DM;      // T_all follows out

    static bool attr_set = false;
    if (!attr_set) {
        cudaFuncSetAttribute(attn_kernel, cudaFuncAttributeMaxDynamicSharedMemorySize, AT_BYTES);
        attr_set = true;
    }

    prep_kernel<<<dim3(8,8), 256>>>(xl, Wq, bq, Wk, bk, W1);
    attn_kernel<<<16, 256, AT_BYTES>>>();
    pair_kernel<<<ROWS, 256>>>(b1, W2, b2);
    expm_kernel<<<1024, 128>>>(xmm, Tout);
    out_kernel<<<32, 256>>>(Wo, bo, out);
}